// round 1
// baseline (speedup 1.0000x reference)
#include <cuda_runtime.h>
#include <cuda_bf16.h>
#include <math.h>

// ---------------- problem constants ----------------
#define N0_NODES 20000
#define N1_NODES 20000
#define N_ALL    40000
#define F0_DIM   512
#define HID      64
#define NHEAD    8
#define DDIM     8
#define NPATH    2
#define E_CNT    200000
#define L_LEN    3
#define BATCH    8192
#define AV_DIM   128
#define CH_DIM   128

// ---------------- device scratch (no allocation allowed) ----------------
__device__ __align__(16) float g_feat[N_ALL * HID];          // 10.24 MB
__device__ __align__(16) float g_fr[4 * 3 * HID];            // per-metapath rotation, [mp][l][64]
__device__ __align__(16) float g_s[4 * BATCH * NHEAD];       // softmax denominators
__device__ __align__(16) float g_ret[4 * BATCH * HID];       // weighted sums
__device__ __align__(16) float g_mpout[4 * BATCH * HID];     // elu(ret/s)
__device__ float g_sem[4];                                   // semantic score accumulators

// ---------------- zero init ----------------
__global__ void k_zero() {
    int i = blockIdx.x * blockDim.x + threadIdx.x;
    const int ns = 4 * BATCH * NHEAD;
    const int nr = 4 * BATCH * HID;
    if (i < ns) g_s[i] = 0.f;
    if (i < nr) g_ret[i] = 0.f;
    if (i < 4)  g_sem[i] = 0.f;
}

// ---------------- rotation precompute ----------------
// rfull order: [r0, conj r0, r1, conj r1]; etypes: user=[0,1], item=[1,0]
// fr[L-1]=identity; fr[i] = fr[i+1] * rfull[et[i]]
__global__ void k_fr(const float* __restrict__ r_vec) {
    int tid = threadIdx.x;
    if (tid >= 128) return;
    int mp = tid >> 5, c = tid & 31;
    int et0 = (mp < 2) ? 0 : 1;
    int et1 = (mp < 2) ? 1 : 0;

    float x0 = r_vec[(et1 >> 1) * 64 + 2 * c], y0 = r_vec[(et1 >> 1) * 64 + 2 * c + 1];
    float n = rsqrtf(x0 * x0 + y0 * y0);
    float f1re = x0 * n, f1im = (et1 & 1) ? -y0 * n : y0 * n;

    float x1 = r_vec[(et0 >> 1) * 64 + 2 * c], y1 = r_vec[(et0 >> 1) * 64 + 2 * c + 1];
    n = rsqrtf(x1 * x1 + y1 * y1);
    float r0re = x1 * n, r0im = (et0 & 1) ? -y1 * n : y1 * n;

    float f0re = f1re * r0re - f1im * r0im;
    float f0im = f1re * r0im + f1im * r0re;

    float* base = g_fr + mp * (3 * HID);
    base[0 * HID + 2 * c] = f0re; base[0 * HID + 2 * c + 1] = f0im;
    base[1 * HID + 2 * c] = f1re; base[1 * HID + 2 * c + 1] = f1im;
    base[2 * HID + 2 * c] = 1.f;  base[2 * HID + 2 * c + 1] = 0.f;
}

// ---------------- feature towers ----------------
// block caches transposed pw (pitch 516 -> conflict-free float4 LDS) + w2 (pitch 68)
#define PW_PITCH 516
#define W2_PITCH 68
#define TOW_SMEM_FLOATS (HID * PW_PITCH + HID * W2_PITCH + 4 * F0_DIM + 4 * HID + 16)
#define TOW_BLOCKS 125
#define TOW_NPB    160   // 125*160 = 20000

__global__ void k_tower(
    const float* __restrict__ f0, const float* __restrict__ f1,
    const float* __restrict__ pw0, const float* __restrict__ pb0,
    const float* __restrict__ w20, const float* __restrict__ b20,
    const float* __restrict__ gm0, const float* __restrict__ be0,
    const float* __restrict__ pw1, const float* __restrict__ pb1,
    const float* __restrict__ w21, const float* __restrict__ b21,
    const float* __restrict__ gm1, const float* __restrict__ be1,
    const int* __restrict__ idx0, const int* __restrict__ idx1)
{
    int t = blockIdx.y;
    const float* feats = t ? f1  : f0;
    const float* pw    = t ? pw1 : pw0;
    const float* pb    = t ? pb1 : pb0;
    const float* w2    = t ? w21 : w20;
    const float* b2    = t ? b21 : b20;
    const float* gmw   = t ? gm1 : gm0;
    const float* bew   = t ? be1 : be0;
    const int*   idx   = t ? idx1 : idx0;

    extern __shared__ float sm[];
    float* pwT = sm;                         // 64*516
    float* w2T = pwT + HID * PW_PITCH;       // 64*68
    float* xs  = w2T + HID * W2_PITCH;       // 4*512
    float* hs  = xs + 4 * F0_DIM;            // 4*64
    float* red = hs + 4 * HID;               // 16

    int tid = threadIdx.x;
    for (int i = tid; i < F0_DIM * HID; i += 256) {
        int k = i >> 6, c = i & 63;
        pwT[c * PW_PITCH + k] = pw[i];
    }
    for (int i = tid; i < HID * HID; i += 256) {
        int k = i >> 6, c = i & 63;
        w2T[c * W2_PITCH + k] = w2[i];
    }
    __syncthreads();

    int c = tid & 63, g = tid >> 6;
    int lane = tid & 31, wig = (tid >> 5) & 1;
    float pbv = pb[c], b2v = b2[c], gv = gmw[c], bev = bew[c];

    int nbeg = blockIdx.x * TOW_NPB;
    int nend = nbeg + TOW_NPB;   // exact division

    for (int nb = nbeg; nb < nend; nb += 4) {
        for (int j = tid; j < 4 * F0_DIM; j += 256) {
            int gg = j >> 9, k = j & 511;
            xs[j] = feats[(size_t)(nb + gg) * F0_DIM + k];
        }
        __syncthreads();

        int node = nb + g;
        float z = pbv;
        const float4* xv = (const float4*)(xs + (g << 9));
        const float4* pv = (const float4*)(pwT + c * PW_PITCH);
        #pragma unroll 8
        for (int q = 0; q < 128; ++q) {
            float4 a = xv[q], bq = pv[q];
            z += a.x * bq.x + a.y * bq.y + a.z * bq.z + a.w * bq.w;
        }
        float h = 0.5f * z * (1.f + erff(z * 0.70710678118654752f));
        hs[(g << 6) + c] = h;
        __syncthreads();

        float y = b2v;
        const float4* hv = (const float4*)(hs + (g << 6));
        const float4* wv = (const float4*)(w2T + c * W2_PITCH);
        #pragma unroll
        for (int q = 0; q < 16; ++q) {
            float4 a = hv[q], bq = wv[q];
            y += a.x * bq.x + a.y * bq.y + a.z * bq.z + a.w * bq.w;
        }
        y += z;

        // layernorm over 64 within group g (2 warps)
        float s1 = y, s2 = y * y;
        #pragma unroll
        for (int o = 16; o > 0; o >>= 1) {
            s1 += __shfl_xor_sync(0xffffffffu, s1, o);
            s2 += __shfl_xor_sync(0xffffffffu, s2, o);
        }
        if (lane == 0) { red[g * 4 + wig * 2] = s1; red[g * 4 + wig * 2 + 1] = s2; }
        __syncthreads();
        float sum = red[g * 4] + red[g * 4 + 2];
        float ssq = red[g * 4 + 1] + red[g * 4 + 3];
        float mu  = sum * (1.f / 64.f);
        float var = ssq * (1.f / 64.f) - mu * mu;
        float outv = (y - mu) * rsqrtf(var + 1e-5f) * gv + bev;
        g_feat[(size_t)idx[node] * HID + c] = outv;
        __syncthreads();
    }
}

// ---------------- metapath gather + edge softmax accumulate ----------------
// 16 lanes per instance; lane owns complex pairs (2*sub, 2*sub+1) = float4.
// Skips segment-max: exp(e)/sum(exp(e)) == reference softmax (|e| bounded << 88).
__global__ void k_metapath(
    const int* __restrict__ emi_u, const int* __restrict__ tgt_u,
    const int* __restrict__ emi_i, const int* __restrict__ tgt_i,
    const float* __restrict__ attn_u, const float* __restrict__ attn_i)
{
    int mp = blockIdx.y;
    const int*   emi  = (mp < 2 ? emi_u : emi_i) + (size_t)(mp & 1) * E_CNT * L_LEN;
    const int*   tgt  = (mp < 2 ? tgt_u : tgt_i) + (size_t)(mp & 1) * E_CNT;
    const float* attn = (mp < 2 ? attn_u : attn_i) + (mp & 1) * HID;

    int tid  = threadIdx.x;
    int sub  = tid & 15;
    int inst = blockIdx.x * (blockDim.x >> 4) + (tid >> 4);  // exact: 12500*16 = 200000

    const float4* fr4 = (const float4*)g_fr + mp * 48;  // [3][16] float4
    float4 fr0 = fr4[sub], fr1 = fr4[16 + sub], fr2 = fr4[32 + sub];
    float4 av = ((const float4*)attn)[sub];

    int n0 = __ldg(emi + inst * 3);
    int n1 = __ldg(emi + inst * 3 + 1);
    int n2 = __ldg(emi + inst * 3 + 2);
    int t  = __ldg(tgt + inst);

    const float4* feat4 = (const float4*)g_feat;
    float4 v0 = __ldg(feat4 + (size_t)n0 * 16 + sub);
    float4 v1 = __ldg(feat4 + (size_t)n1 * 16 + sub);
    float4 v2 = __ldg(feat4 + (size_t)n2 * 16 + sub);

    float hx = (v0.x * fr0.x - v0.y * fr0.y) + (v1.x * fr1.x - v1.y * fr1.y) + (v2.x * fr2.x - v2.y * fr2.y);
    float hy = (v0.x * fr0.y + v0.y * fr0.x) + (v1.x * fr1.y + v1.y * fr1.x) + (v2.x * fr2.y + v2.y * fr2.x);
    float hz = (v0.z * fr0.z - v0.w * fr0.w) + (v1.z * fr1.z - v1.w * fr1.w) + (v2.z * fr2.z - v2.w * fr2.w);
    float hw = (v0.z * fr0.w + v0.w * fr0.z) + (v1.z * fr1.w + v1.w * fr1.z) + (v2.z * fr2.w + v2.w * fr2.z);
    const float inv3 = (1.f / 3.f);
    hx *= inv3; hy *= inv3; hz *= inv3; hw *= inv3;

    float p = hx * av.x + hy * av.y + hz * av.z + hw * av.w;
    p += __shfl_xor_sync(0xffffffffu, p, 1);
    float e = p > 0.f ? p : 0.01f * p;
    float a = expf(e);

    size_t base = (size_t)mp * BATCH + t;
    if (!(sub & 1)) atomicAdd(&g_s[base * NHEAD + (sub >> 1)], a);
    float* rb = g_ret + base * HID + sub * 4;
    atomicAdd(rb + 0, a * hx);
    atomicAdd(rb + 1, a * hy);
    atomicAdd(rb + 2, a * hz);
    atomicAdd(rb + 3, a * hw);
}

// ---------------- normalize + elu + semantic score accumulation ----------------
__global__ void k_norm_sem(
    const float* __restrict__ su_w1, const float* __restrict__ su_b1, const float* __restrict__ su_w2,
    const float* __restrict__ si_w1, const float* __restrict__ si_b1, const float* __restrict__ si_w2)
{
    int mp = blockIdx.y, b = blockIdx.x, tid = threadIdx.x;
    __shared__ float sh[HID];
    __shared__ float red[AV_DIM];

    size_t base = ((size_t)mp * BATCH + b) * HID;
    if (tid < HID) {
        float sv = g_s[((size_t)mp * BATCH + b) * NHEAD + (tid >> 3)];
        float v = g_ret[base + tid] / (sv + 1e-9f);
        v = v > 0.f ? v : expf(v) - 1.f;
        g_mpout[base + tid] = v;
        sh[tid] = v;
    }
    __syncthreads();

    const float* w1 = (mp < 2) ? su_w1 : si_w1;
    const float* b1 = (mp < 2) ? su_b1 : si_b1;
    const float* w2 = (mp < 2) ? su_w2 : si_w2;

    float acc = b1[tid];
    #pragma unroll
    for (int k = 0; k < HID; ++k) acc += sh[k] * __ldg(&w1[k * AV_DIM + tid]);
    red[tid] = tanhf(acc) * w2[tid];
    __syncthreads();
    for (int s = AV_DIM / 2; s > 0; s >>= 1) {
        if (tid < s) red[tid] += red[tid + s];
        __syncthreads();
    }
    if (tid == 0) atomicAdd(&g_sem[mp], red[0]);
}

// ---------------- semantic fusion + product MLP + softmax ----------------
__global__ void k_final(const float* __restrict__ cw1, const float* __restrict__ cb1,
                        const float* __restrict__ cw2, float* __restrict__ out)
{
    int b = blockIdx.x, tid = threadIdx.x;
    __shared__ float xs[HID];
    __shared__ float r0[CH_DIM], r1[CH_DIM];

    float s0 = g_sem[0] * (1.f / BATCH), s1 = g_sem[1] * (1.f / BATCH);
    float s2 = g_sem[2] * (1.f / BATCH), s3 = g_sem[3] * (1.f / BATCH);
    float mU = fmaxf(s0, s1), mI = fmaxf(s2, s3);
    float e0 = expf(s0 - mU), e1 = expf(s1 - mU);
    float e2 = expf(s2 - mI), e3 = expf(s3 - mI);
    float bu0 = e0 / (e0 + e1), bu1 = e1 / (e0 + e1);
    float bi0 = e2 / (e2 + e3), bi1 = e3 / (e2 + e3);

    if (tid < HID) {
        float hu = bu0 * g_mpout[((size_t)0 * BATCH + b) * HID + tid]
                 + bu1 * g_mpout[((size_t)1 * BATCH + b) * HID + tid];
        float hi = bi0 * g_mpout[((size_t)2 * BATCH + b) * HID + tid]
                 + bi1 * g_mpout[((size_t)3 * BATCH + b) * HID + tid];
        xs[tid] = hu * hi;
    }
    __syncthreads();

    float acc = cb1[tid];
    #pragma unroll
    for (int k = 0; k < HID; ++k) acc += xs[k] * __ldg(&cw1[k * CH_DIM + tid]);
    acc = fmaxf(acc, 0.f);
    r0[tid] = acc * cw2[tid * 2];
    r1[tid] = acc * cw2[tid * 2 + 1];
    __syncthreads();
    for (int s = CH_DIM / 2; s > 0; s >>= 1) {
        if (tid < s) { r0[tid] += r0[tid + s]; r1[tid] += r1[tid + s]; }
        __syncthreads();
    }
    if (tid == 0) {
        float l0 = r0[0], l1 = r1[0];
        float m = fmaxf(l0, l1);
        float a0 = expf(l0 - m), a1 = expf(l1 - m);
        float inv = 1.f / (a0 + a1);
        out[b * 2 + 0] = a0 * inv;
        out[b * 2 + 1] = a1 * inv;
    }
}

// ---------------- launch ----------------
extern "C" void kernel_launch(void* const* d_in, const int* in_sizes, int n_in,
                              void* d_out, int out_size) {
    (void)in_sizes; (void)n_in; (void)out_size;
    const float* feats0 = (const float*)d_in[0];
    const float* feats1 = (const float*)d_in[1];
    const float* t0_pw = (const float*)d_in[2];
    const float* t0_pb = (const float*)d_in[3];
    const float* t0_w2 = (const float*)d_in[4];
    const float* t0_b2 = (const float*)d_in[5];
    const float* t0_g  = (const float*)d_in[6];
    const float* t0_be = (const float*)d_in[7];
    const float* t1_pw = (const float*)d_in[8];
    const float* t1_pb = (const float*)d_in[9];
    const float* t1_w2 = (const float*)d_in[10];
    const float* t1_b2 = (const float*)d_in[11];
    const float* t1_g  = (const float*)d_in[12];
    const float* t1_be = (const float*)d_in[13];
    const float* r_vec = (const float*)d_in[14];
    const float* attn_user = (const float*)d_in[15];
    const float* attn_item = (const float*)d_in[16];
    const float* su_w1 = (const float*)d_in[17];
    const float* su_b1 = (const float*)d_in[18];
    const float* su_w2 = (const float*)d_in[19];
    const float* si_w1 = (const float*)d_in[20];
    const float* si_b1 = (const float*)d_in[21];
    const float* si_w2 = (const float*)d_in[22];
    const float* cw1   = (const float*)d_in[23];
    const float* cb1   = (const float*)d_in[24];
    const float* cw2   = (const float*)d_in[25];
    const int* idx0 = (const int*)d_in[26];
    const int* idx1 = (const int*)d_in[27];
    const int* emi_user = (const int*)d_in[28];
    const int* tgt_user = (const int*)d_in[29];
    const int* emi_item = (const int*)d_in[30];
    const int* tgt_item = (const int*)d_in[31];
    float* out = (float*)d_out;

    const int tower_smem = TOW_SMEM_FLOATS * sizeof(float);
    cudaFuncSetAttribute(k_tower, cudaFuncAttributeMaxDynamicSharedMemorySize, tower_smem);

    k_zero<<<8192, 256>>>();
    k_fr<<<1, 128>>>(r_vec);

    dim3 tg(TOW_BLOCKS, 2);
    k_tower<<<tg, 256, tower_smem>>>(feats0, feats1,
        t0_pw, t0_pb, t0_w2, t0_b2, t0_g, t0_be,
        t1_pw, t1_pb, t1_w2, t1_b2, t1_g, t1_be,
        idx0, idx1);

    dim3 mg(E_CNT / 16, 4);
    k_metapath<<<mg, 256>>>(emi_user, tgt_user, emi_item, tgt_item, attn_user, attn_item);

    dim3 ng(BATCH, 4);
    k_norm_sem<<<ng, 128>>>(su_w1, su_b1, su_w2, si_w1, si_b1, si_w2);

    k_final<<<BATCH, 128>>>(cw1, cb1, cw2, out);
}

// round 2
// speedup vs baseline: 1.9311x; 1.9311x over previous
#include <cuda_runtime.h>
#include <cuda_bf16.h>
#include <math.h>

// ---------------- problem constants ----------------
#define N0_NODES 20000
#define N_ALL    40000
#define F0_DIM   512
#define HID      64
#define NHEAD    8
#define E_CNT    200000
#define BATCH    8192
#define AV_DIM   128
#define CH_DIM   128

typedef unsigned long long ull;

__device__ __forceinline__ ull pack2(float lo, float hi) {
    ull r; asm("mov.b64 %0, {%1, %2};" : "=l"(r) : "f"(lo), "f"(hi)); return r;
}
__device__ __forceinline__ void unpack2(ull v, float& lo, float& hi) {
    asm("mov.b64 {%0, %1}, %2;" : "=f"(lo), "=f"(hi) : "l"(v));
}
__device__ __forceinline__ void ffma2(ull& d, ull a, ull b) {
    asm("fma.rn.f32x2 %0, %1, %2, %0;" : "+l"(d) : "l"(a), "l"(b));
}
__device__ __forceinline__ ull fadd2(ull a, ull b) {
    ull r; asm("add.rn.f32x2 %0, %1, %2;" : "=l"(r) : "l"(a), "l"(b)); return r;
}

// ---------------- device scratch ----------------
__device__ __align__(16) float g_feat[N_ALL * HID];
__device__ __align__(16) float g_fr[4 * 3 * HID];
__device__ __align__(16) float g_s[4 * BATCH * NHEAD];
__device__ __align__(16) float g_ret[4 * BATCH * HID];
__device__ __align__(16) float g_mpout[4 * BATCH * HID];
__device__ float g_sem[4];

// ---------------- zero init ----------------
__global__ void k_zero() {
    int i = blockIdx.x * blockDim.x + threadIdx.x;
    const int ns = 4 * BATCH * NHEAD;
    const int nr = 4 * BATCH * HID;
    if (i < ns) g_s[i] = 0.f;
    if (i < nr) g_ret[i] = 0.f;
    if (i < 4)  g_sem[i] = 0.f;
}

// ---------------- rotation precompute ----------------
__global__ void k_fr(const float* __restrict__ r_vec) {
    int tid = threadIdx.x;
    if (tid >= 128) return;
    int mp = tid >> 5, c = tid & 31;
    int et0 = (mp < 2) ? 0 : 1;
    int et1 = (mp < 2) ? 1 : 0;

    float x0 = r_vec[(et1 >> 1) * 64 + 2 * c], y0 = r_vec[(et1 >> 1) * 64 + 2 * c + 1];
    float n = rsqrtf(x0 * x0 + y0 * y0);
    float f1re = x0 * n, f1im = (et1 & 1) ? -y0 * n : y0 * n;

    float x1 = r_vec[(et0 >> 1) * 64 + 2 * c], y1 = r_vec[(et0 >> 1) * 64 + 2 * c + 1];
    n = rsqrtf(x1 * x1 + y1 * y1);
    float r0re = x1 * n, r0im = (et0 & 1) ? -y1 * n : y1 * n;

    float f0re = f1re * r0re - f1im * r0im;
    float f0im = f1re * r0im + f1im * r0re;

    float* base = g_fr + mp * (3 * HID);
    base[0 * HID + 2 * c] = f0re; base[0 * HID + 2 * c + 1] = f0im;
    base[1 * HID + 2 * c] = f1re; base[1 * HID + 2 * c + 1] = f1im;
    base[2 * HID + 2 * c] = 1.f;  base[2 * HID + 2 * c + 1] = 0.f;
}

// ---------------- feature towers: register-tiled GEMM + f32x2 ----------------
// Block: 128 nodes x 64 cols. 256 threads as 16(ty) x 16(tx).
// Thread: 8 nodes (4 packed pairs) x 4 cols. smem x layout: [pair][k][2] packed.
#define TOW_BM 128
#define TOW_KB 64
// xs: 64 pairs * 128 (k*2) floats = 32KB ; ws: 64*64 = 16KB
#define TOW_SMEM ((64 * 128 + 64 * 64) * 4)

__device__ __forceinline__ float gelu_exact(float z) {
    return 0.5f * z * (1.f + erff(z * 0.70710678118654752f));
}

__global__ void __launch_bounds__(256, 2) k_tower(
    const float* __restrict__ f0, const float* __restrict__ f1,
    const float* __restrict__ pw0, const float* __restrict__ pb0,
    const float* __restrict__ w20, const float* __restrict__ b20,
    const float* __restrict__ gm0, const float* __restrict__ be0,
    const float* __restrict__ pw1, const float* __restrict__ pb1,
    const float* __restrict__ w21, const float* __restrict__ b21,
    const float* __restrict__ gm1, const float* __restrict__ be1,
    const int* __restrict__ idx0, const int* __restrict__ idx1)
{
    int t = blockIdx.y;
    const float* feats = t ? f1  : f0;
    const float* pw    = t ? pw1 : pw0;
    const float* pb    = t ? pb1 : pb0;
    const float* w2    = t ? w21 : w20;
    const float* b2    = t ? b21 : b20;
    const float* gmw   = t ? gm1 : gm0;
    const float* bew   = t ? be1 : be0;
    const int*   idx   = t ? idx1 : idx0;

    extern __shared__ float sm[];
    float* xs = sm;              // [64 pairs][128] (k interleaved x2)
    float* ws = sm + 64 * 128;   // [64 k][64 c]

    int tid = threadIdx.x;
    int tx = tid & 15, ty = tid >> 4;
    int nb = blockIdx.x * TOW_BM;

    float4 pbv = *(const float4*)(pb + tx * 4);
    ull acc[4][4];
    #pragma unroll
    for (int i = 0; i < 4; ++i) {
        acc[i][0] = pack2(pbv.x, pbv.x);
        acc[i][1] = pack2(pbv.y, pbv.y);
        acc[i][2] = pack2(pbv.z, pbv.z);
        acc[i][3] = pack2(pbv.w, pbv.w);
    }

    // ---- GEMM1: z = x @ pw + pb, k in 8 chunks of 64 ----
    for (int kc = 0; kc < F0_DIM; kc += TOW_KB) {
        #pragma unroll
        for (int r = 0; r < 8; ++r) {
            int i = tid + r * 256;
            int node = i >> 4, kq = i & 15;
            int ng = nb + node;
            float4 v = make_float4(0.f, 0.f, 0.f, 0.f);
            if (ng < N0_NODES) v = *(const float4*)(feats + (size_t)ng * F0_DIM + kc + kq * 4);
            float* xb = xs + (node >> 1) * 128 + (node & 1);
            xb[(kq * 4 + 0) * 2] = v.x;
            xb[(kq * 4 + 1) * 2] = v.y;
            xb[(kq * 4 + 2) * 2] = v.z;
            xb[(kq * 4 + 3) * 2] = v.w;
        }
        #pragma unroll
        for (int r = 0; r < 4; ++r) {
            int i = tid + r * 256;
            int k = i >> 4, cq = i & 15;
            *(float4*)(ws + k * 64 + cq * 4) = *(const float4*)(pw + (size_t)(kc + k) * HID + cq * 4);
        }
        __syncthreads();

        #pragma unroll 4
        for (int k = 0; k < TOW_KB; ++k) {
            float4 wv = *(const float4*)(ws + k * 64 + tx * 4);
            ull w0 = pack2(wv.x, wv.x), w1 = pack2(wv.y, wv.y);
            ull w2p = pack2(wv.z, wv.z), w3 = pack2(wv.w, wv.w);
            #pragma unroll
            for (int i = 0; i < 4; ++i) {
                ull xv = *(const ull*)(xs + (ty * 4 + i) * 128 + 2 * k);
                ffma2(acc[i][0], xv, w0);
                ffma2(acc[i][1], xv, w1);
                ffma2(acc[i][2], xv, w2p);
                ffma2(acc[i][3], xv, w3);
            }
        }
        __syncthreads();
    }

    // ---- GELU, store h packed into xs; load w2 into ws ----
    #pragma unroll
    for (int i = 0; i < 4; ++i)
        #pragma unroll
        for (int j = 0; j < 4; ++j) {
            float zl, zh;
            unpack2(acc[i][j], zl, zh);
            float* hb = xs + (ty * 4 + i) * 128 + (tx * 4 + j) * 2;
            hb[0] = gelu_exact(zl);
            hb[1] = gelu_exact(zh);
        }
    #pragma unroll
    for (int r = 0; r < 4; ++r) {
        int i = tid + r * 256;
        int k = i >> 4, cq = i & 15;
        *(float4*)(ws + k * 64 + cq * 4) = *(const float4*)(w2 + (size_t)k * HID + cq * 4);
    }
    __syncthreads();

    // ---- GEMM2: y = h @ w2 + b2 + z ----
    float4 b2v = *(const float4*)(b2 + tx * 4);
    ull yacc[4][4];
    #pragma unroll
    for (int i = 0; i < 4; ++i) {
        yacc[i][0] = fadd2(acc[i][0], pack2(b2v.x, b2v.x));
        yacc[i][1] = fadd2(acc[i][1], pack2(b2v.y, b2v.y));
        yacc[i][2] = fadd2(acc[i][2], pack2(b2v.z, b2v.z));
        yacc[i][3] = fadd2(acc[i][3], pack2(b2v.w, b2v.w));
    }
    #pragma unroll 4
    for (int k = 0; k < HID; ++k) {
        float4 wv = *(const float4*)(ws + k * 64 + tx * 4);
        ull w0 = pack2(wv.x, wv.x), w1 = pack2(wv.y, wv.y);
        ull w2p = pack2(wv.z, wv.z), w3 = pack2(wv.w, wv.w);
        #pragma unroll
        for (int i = 0; i < 4; ++i) {
            ull xv = *(const ull*)(xs + (ty * 4 + i) * 128 + 2 * k);
            ffma2(yacc[i][0], xv, w0);
            ffma2(yacc[i][1], xv, w1);
            ffma2(yacc[i][2], xv, w2p);
            ffma2(yacc[i][3], xv, w3);
        }
    }

    // ---- LayerNorm via shuffle across tx (16 lanes) ----
    float y[8][4];
    #pragma unroll
    for (int i = 0; i < 4; ++i)
        #pragma unroll
        for (int j = 0; j < 4; ++j)
            unpack2(yacc[i][j], y[2 * i][j], y[2 * i + 1][j]);

    float4 gv = *(const float4*)(gmw + tx * 4);
    float4 bev = *(const float4*)(bew + tx * 4);

    #pragma unroll
    for (int i = 0; i < 8; ++i) {
        float s1 = y[i][0] + y[i][1] + y[i][2] + y[i][3];
        float s2 = y[i][0] * y[i][0] + y[i][1] * y[i][1] + y[i][2] * y[i][2] + y[i][3] * y[i][3];
        #pragma unroll
        for (int o = 8; o > 0; o >>= 1) {
            s1 += __shfl_xor_sync(0xffffffffu, s1, o);
            s2 += __shfl_xor_sync(0xffffffffu, s2, o);
        }
        float mu  = s1 * (1.f / 64.f);
        float var = s2 * (1.f / 64.f) - mu * mu;
        float rs  = rsqrtf(var + 1e-5f);
        int ng = nb + ty * 8 + i;
        if (ng < N0_NODES) {
            int dst = idx[ng];
            float4 o4;
            o4.x = (y[i][0] - mu) * rs * gv.x + bev.x;
            o4.y = (y[i][1] - mu) * rs * gv.y + bev.y;
            o4.z = (y[i][2] - mu) * rs * gv.z + bev.z;
            o4.w = (y[i][3] - mu) * rs * gv.w + bev.w;
            *(float4*)(g_feat + (size_t)dst * HID + tx * 4) = o4;
        }
    }
}

// ---------------- metapath gather + edge softmax accumulate ----------------
__global__ void k_metapath(
    const int* __restrict__ emi_u, const int* __restrict__ tgt_u,
    const int* __restrict__ emi_i, const int* __restrict__ tgt_i,
    const float* __restrict__ attn_u, const float* __restrict__ attn_i)
{
    int mp = blockIdx.y;
    const int*   emi  = (mp < 2 ? emi_u : emi_i) + (size_t)(mp & 1) * E_CNT * 3;
    const int*   tgt  = (mp < 2 ? tgt_u : tgt_i) + (size_t)(mp & 1) * E_CNT;
    const float* attn = (mp < 2 ? attn_u : attn_i) + (mp & 1) * HID;

    int tid  = threadIdx.x;
    int sub  = tid & 15;
    int inst = blockIdx.x * (blockDim.x >> 4) + (tid >> 4);

    const float4* fr4 = (const float4*)g_fr + mp * 48;
    float4 fr0 = fr4[sub], fr1 = fr4[16 + sub], fr2 = fr4[32 + sub];
    float4 av = ((const float4*)attn)[sub];

    int n0 = __ldg(emi + inst * 3);
    int n1 = __ldg(emi + inst * 3 + 1);
    int n2 = __ldg(emi + inst * 3 + 2);
    int t  = __ldg(tgt + inst);

    const float4* feat4 = (const float4*)g_feat;
    float4 v0 = __ldg(feat4 + (size_t)n0 * 16 + sub);
    float4 v1 = __ldg(feat4 + (size_t)n1 * 16 + sub);
    float4 v2 = __ldg(feat4 + (size_t)n2 * 16 + sub);

    float hx = (v0.x * fr0.x - v0.y * fr0.y) + (v1.x * fr1.x - v1.y * fr1.y) + (v2.x * fr2.x - v2.y * fr2.y);
    float hy = (v0.x * fr0.y + v0.y * fr0.x) + (v1.x * fr1.y + v1.y * fr1.x) + (v2.x * fr2.y + v2.y * fr2.x);
    float hz = (v0.z * fr0.z - v0.w * fr0.w) + (v1.z * fr1.z - v1.w * fr1.w) + (v2.z * fr2.z - v2.w * fr2.w);
    float hw = (v0.z * fr0.w + v0.w * fr0.z) + (v1.z * fr1.w + v1.w * fr1.z) + (v2.z * fr2.w + v2.w * fr2.z);
    const float inv3 = (1.f / 3.f);
    hx *= inv3; hy *= inv3; hz *= inv3; hw *= inv3;

    float p = hx * av.x + hy * av.y + hz * av.z + hw * av.w;
    p += __shfl_xor_sync(0xffffffffu, p, 1);
    float e = p > 0.f ? p : 0.01f * p;
    float a = expf(e);

    size_t base = (size_t)mp * BATCH + t;
    if (!(sub & 1)) atomicAdd(&g_s[base * NHEAD + (sub >> 1)], a);
    float* rb = g_ret + base * HID + sub * 4;
    atomicAdd(rb + 0, a * hx);
    atomicAdd(rb + 1, a * hy);
    atomicAdd(rb + 2, a * hz);
    atomicAdd(rb + 3, a * hw);
}

// ---------------- normalize + elu + semantic scores (batched, w1 cached) ----------------
#define NS_BB 16
__global__ void __launch_bounds__(128) k_norm_sem(
    const float* __restrict__ su_w1, const float* __restrict__ su_b1, const float* __restrict__ su_w2,
    const float* __restrict__ si_w1, const float* __restrict__ si_b1, const float* __restrict__ si_w2)
{
    int mp = blockIdx.y, tid = threadIdx.x;
    __shared__ float w1s[HID * AV_DIM];
    __shared__ float sh[HID];
    __shared__ float red[4];

    const float* w1 = (mp < 2) ? su_w1 : si_w1;
    const float* b1 = (mp < 2) ? su_b1 : si_b1;
    const float* w2 = (mp < 2) ? su_w2 : si_w2;

    for (int i = tid; i < HID * AV_DIM; i += 128) w1s[i] = w1[i];
    float b1v = b1[tid], w2v = w2[tid];
    __syncthreads();

    float local = 0.f;
    for (int bb = 0; bb < NS_BB; ++bb) {
        int b = blockIdx.x * NS_BB + bb;
        size_t base = ((size_t)mp * BATCH + b) * HID;
        if (tid < HID) {
            float sv = g_s[((size_t)mp * BATCH + b) * NHEAD + (tid >> 3)];
            float v = g_ret[base + tid] / (sv + 1e-9f);
            v = v > 0.f ? v : expf(v) - 1.f;
            g_mpout[base + tid] = v;
            sh[tid] = v;
        }
        __syncthreads();

        float acc = b1v;
        #pragma unroll
        for (int k = 0; k < HID; ++k) acc += sh[k] * w1s[k * AV_DIM + tid];
        float v = tanhf(acc) * w2v;
        #pragma unroll
        for (int o = 16; o > 0; o >>= 1) v += __shfl_xor_sync(0xffffffffu, v, o);
        if ((tid & 31) == 0) red[tid >> 5] = v;
        __syncthreads();
        if (tid == 0) local += red[0] + red[1] + red[2] + red[3];
        __syncthreads();
    }
    if (tid == 0) atomicAdd(&g_sem[mp], local);
}

// ---------------- semantic fusion + product MLP + softmax (batched) ----------------
#define KF_BB 16
__global__ void __launch_bounds__(128) k_final(
    const float* __restrict__ cw1, const float* __restrict__ cb1,
    const float* __restrict__ cw2, float* __restrict__ out)
{
    int tid = threadIdx.x;
    __shared__ float cw1s[HID * CH_DIM];
    __shared__ float xsb[HID];
    __shared__ float r0s[4], r1s[4];

    for (int i = tid; i < HID * CH_DIM; i += 128) cw1s[i] = cw1[i];
    float cb1v = cb1[tid];
    float cw20 = cw2[tid * 2], cw21 = cw2[tid * 2 + 1];

    float s0 = g_sem[0] * (1.f / BATCH), s1 = g_sem[1] * (1.f / BATCH);
    float s2 = g_sem[2] * (1.f / BATCH), s3 = g_sem[3] * (1.f / BATCH);
    float mU = fmaxf(s0, s1), mI = fmaxf(s2, s3);
    float e0 = expf(s0 - mU), e1 = expf(s1 - mU);
    float e2 = expf(s2 - mI), e3 = expf(s3 - mI);
    float bu0 = e0 / (e0 + e1), bu1 = e1 / (e0 + e1);
    float bi0 = e2 / (e2 + e3), bi1 = e3 / (e2 + e3);
    __syncthreads();

    for (int bb = 0; bb < KF_BB; ++bb) {
        int b = blockIdx.x * KF_BB + bb;
        if (tid < HID) {
            float hu = bu0 * g_mpout[((size_t)0 * BATCH + b) * HID + tid]
                     + bu1 * g_mpout[((size_t)1 * BATCH + b) * HID + tid];
            float hi = bi0 * g_mpout[((size_t)2 * BATCH + b) * HID + tid]
                     + bi1 * g_mpout[((size_t)3 * BATCH + b) * HID + tid];
            xsb[tid] = hu * hi;
        }
        __syncthreads();

        float acc = cb1v;
        #pragma unroll
        for (int k = 0; k < HID; ++k) acc += xsb[k] * cw1s[k * CH_DIM + tid];
        acc = fmaxf(acc, 0.f);
        float v0 = acc * cw20, v1 = acc * cw21;
        #pragma unroll
        for (int o = 16; o > 0; o >>= 1) {
            v0 += __shfl_xor_sync(0xffffffffu, v0, o);
            v1 += __shfl_xor_sync(0xffffffffu, v1, o);
        }
        if ((tid & 31) == 0) { r0s[tid >> 5] = v0; r1s[tid >> 5] = v1; }
        __syncthreads();
        if (tid == 0) {
            float l0 = r0s[0] + r0s[1] + r0s[2] + r0s[3];
            float l1 = r1s[0] + r1s[1] + r1s[2] + r1s[3];
            float m = fmaxf(l0, l1);
            float a0 = expf(l0 - m), a1 = expf(l1 - m);
            float inv = 1.f / (a0 + a1);
            out[b * 2 + 0] = a0 * inv;
            out[b * 2 + 1] = a1 * inv;
        }
        __syncthreads();
    }
}

// ---------------- launch ----------------
extern "C" void kernel_launch(void* const* d_in, const int* in_sizes, int n_in,
                              void* d_out, int out_size) {
    (void)in_sizes; (void)n_in; (void)out_size;
    const float* feats0 = (const float*)d_in[0];
    const float* feats1 = (const float*)d_in[1];
    const float* t0_pw = (const float*)d_in[2];
    const float* t0_pb = (const float*)d_in[3];
    const float* t0_w2 = (const float*)d_in[4];
    const float* t0_b2 = (const float*)d_in[5];
    const float* t0_g  = (const float*)d_in[6];
    const float* t0_be = (const float*)d_in[7];
    const float* t1_pw = (const float*)d_in[8];
    const float* t1_pb = (const float*)d_in[9];
    const float* t1_w2 = (const float*)d_in[10];
    const float* t1_b2 = (const float*)d_in[11];
    const float* t1_g  = (const float*)d_in[12];
    const float* t1_be = (const float*)d_in[13];
    const float* r_vec = (const float*)d_in[14];
    const float* attn_user = (const float*)d_in[15];
    const float* attn_item = (const float*)d_in[16];
    const float* su_w1 = (const float*)d_in[17];
    const float* su_b1 = (const float*)d_in[18];
    const float* su_w2 = (const float*)d_in[19];
    const float* si_w1 = (const float*)d_in[20];
    const float* si_b1 = (const float*)d_in[21];
    const float* si_w2 = (const float*)d_in[22];
    const float* cw1   = (const float*)d_in[23];
    const float* cb1   = (const float*)d_in[24];
    const float* cw2   = (const float*)d_in[25];
    const int* idx0 = (const int*)d_in[26];
    const int* idx1 = (const int*)d_in[27];
    const int* emi_user = (const int*)d_in[28];
    const int* tgt_user = (const int*)d_in[29];
    const int* emi_item = (const int*)d_in[30];
    const int* tgt_item = (const int*)d_in[31];
    float* out = (float*)d_out;

    cudaFuncSetAttribute(k_tower, cudaFuncAttributeMaxDynamicSharedMemorySize, TOW_SMEM);

    k_zero<<<8192, 256>>>();
    k_fr<<<1, 128>>>(r_vec);

    dim3 tg((N0_NODES + TOW_BM - 1) / TOW_BM, 2);
    k_tower<<<tg, 256, TOW_SMEM>>>(feats0, feats1,
        t0_pw, t0_pb, t0_w2, t0_b2, t0_g, t0_be,
        t1_pw, t1_pb, t1_w2, t1_b2, t1_g, t1_be,
        idx0, idx1);

    dim3 mg(E_CNT / 16, 4);
    k_metapath<<<mg, 256>>>(emi_user, tgt_user, emi_item, tgt_item, attn_user, attn_item);

    dim3 ng(BATCH / NS_BB, 4);
    k_norm_sem<<<ng, 128>>>(su_w1, su_b1, su_w2, si_w1, si_b1, si_w2);

    k_final<<<BATCH / KF_BB, 128>>>(cw1, cb1, cw2, out);
}